// round 1
// baseline (speedup 1.0000x reference)
#include <cuda_runtime.h>
#include <cstdint>
#include <cstddef>

#define T_STEPS 10
#define NB 8

// ---------------- scratch (device globals; no allocation) ----------------
__device__ uint32_t g_spk1[T_STEPS*NB*128*160];      // 32ch masks, 6.6MB
__device__ uint32_t g_spk2[T_STEPS*NB*64*80*2];      // 64ch masks, 3.3MB
__device__ uint32_t g_spk3[T_STEPS*NB*32*40*2];      // 64ch masks
__device__ uint32_t g_spk4[T_STEPS*NB*16*20*4];      // 128ch masks
__device__ float    g_S[10240*NB];                   // spike counts, [k][b]
__device__ float    g_spk1f[NB*4096];                // fc1 spikes

// ---------------- layer 1: conv 2->32 @256x320 + LIF + pool ----------------
__global__ void __launch_bounds__(256) k_l1(const float* __restrict__ x,
                                            const float* __restrict__ w1,
                                            const float* __restrict__ b1) {
    int tid = blockIdx.x*256 + threadIdx.x;          // 655360 total
    int g   = tid & 3;                               // channel group (8 ch)
    int wp  = (tid >> 2) % 160;
    int hp  = ((tid >> 2) / 160) % 128;
    int b   = (tid >> 2) / (160*128);

    float wr0[8], wr1[8], bb[8];
    #pragma unroll
    for (int oo=0; oo<8; oo++) {
        int o = g*8+oo;
        wr0[oo] = w1[2*o]; wr1[oo] = w1[2*o+1]; bb[oo] = b1[o];
    }
    float m[4][8];
    #pragma unroll
    for (int p=0;p<4;p++)
        #pragma unroll
        for (int oo=0;oo<8;oo++) m[p][oo]=0.0f;

    uint8_t* outb = (uint8_t*)g_spk1;
    #pragma unroll 1
    for (int t=0; t<T_STEPS; t++) {
        const float* xb = x + ((size_t)(t*NB+b))*(2*256*320) + (2*hp)*320 + 2*wp;
        float x0[4], x1[4];
        #pragma unroll
        for (int p=0;p<4;p++) {
            int dh=p>>1, dw=p&1;
            x0[p] = xb[dh*320+dw];
            x1[p] = xb[81920 + dh*320+dw];
        }
        uint32_t bits=0;
        #pragma unroll
        for (int oo=0;oo<8;oo++) {
            uint32_t pb=0;
            #pragma unroll
            for (int p=0;p<4;p++) {
                float cur = fmaf(wr1[oo], x1[p], wr0[oo]*x0[p]) + bb[oo];
                float mo  = m[p][oo];
                float mn  = fmaf(0.95f, mo, cur) - ((mo>1.0f)?1.0f:0.0f);
                m[p][oo]  = mn;
                pb |= (mn>1.0f)?1u:0u;
            }
            bits |= pb<<oo;
        }
        outb[(((size_t)(t*NB+b)*128 + hp)*160 + wp)*4 + g] = (uint8_t)bits;
    }
}

// ------------- generic conv(1x1 over bitmask spikes)+LIF+pool, 8 out ch/thread -------------
template<int CIN, int COUT, int HIN, int WIN>
__device__ __forceinline__ void conv_lif_body(const uint32_t* __restrict__ in_masks,
                                              uint8_t* __restrict__ out_bytes,
                                              const float* __restrict__ wg,
                                              const float* __restrict__ bg,
                                              float* wt) {
    constexpr int WRD = CIN/32;
    constexpr int NG  = COUT/8;
    constexpr int HP  = HIN/2, WP = WIN/2;

    // stage transposed weights: wt[c][o]
    for (int idx=threadIdx.x; idx<CIN*COUT; idx+=256) {
        int o = idx / CIN, c = idx % CIN;
        wt[c*COUT + o] = wg[idx];
    }
    __syncthreads();

    int tid = blockIdx.x*256 + threadIdx.x;
    int og  = tid % NG;
    int wp  = (tid/NG) % WP;
    int hp  = (tid/(NG*WP)) % HP;
    int b   = tid/(NG*WP*HP);

    float bb[8];
    #pragma unroll
    for (int oo=0;oo<8;oo++) bb[oo]=bg[og*8+oo];
    float m[4][8];
    #pragma unroll
    for (int p=0;p<4;p++)
        #pragma unroll
        for (int oo=0;oo<8;oo++) m[p][oo]=0.0f;

    #pragma unroll 1
    for (int t=0;t<T_STEPS;t++) {
        uint32_t msk[4][WRD];
        const uint32_t* ip = in_masks + (((size_t)(t*NB+b)*HIN + 2*hp)*WIN + 2*wp)*WRD;
        #pragma unroll
        for (int p=0;p<4;p++) {
            int dh=p>>1, dw=p&1;
            #pragma unroll
            for (int w=0;w<WRD;w++)
                msk[p][w] = ip[((size_t)dh*WIN + dw)*WRD + w];
        }
        float cur[4][8];
        #pragma unroll
        for (int p=0;p<4;p++)
            #pragma unroll
            for (int oo=0;oo<8;oo++) cur[p][oo]=0.0f;

        #pragma unroll
        for (int w=0;w<WRD;w++) {
            #pragma unroll
            for (int cb=0;cb<32;cb++) {
                const float* wrow = wt + (w*32+cb)*COUT + og*8;
                float4 wa = *(const float4*)wrow;
                float4 wb = *(const float4*)(wrow+4);
                #pragma unroll
                for (int p=0;p<4;p++) {
                    float s = (float)((msk[p][w]>>cb)&1u);
                    cur[p][0]=fmaf(wa.x,s,cur[p][0]);
                    cur[p][1]=fmaf(wa.y,s,cur[p][1]);
                    cur[p][2]=fmaf(wa.z,s,cur[p][2]);
                    cur[p][3]=fmaf(wa.w,s,cur[p][3]);
                    cur[p][4]=fmaf(wb.x,s,cur[p][4]);
                    cur[p][5]=fmaf(wb.y,s,cur[p][5]);
                    cur[p][6]=fmaf(wb.z,s,cur[p][6]);
                    cur[p][7]=fmaf(wb.w,s,cur[p][7]);
                }
            }
        }
        uint32_t bits=0;
        #pragma unroll
        for (int oo=0;oo<8;oo++) {
            uint32_t pb=0;
            #pragma unroll
            for (int p=0;p<4;p++) {
                float cf = cur[p][oo] + bb[oo];
                float mo = m[p][oo];
                float mn = fmaf(0.95f, mo, cf) - ((mo>1.0f)?1.0f:0.0f);
                m[p][oo] = mn;
                pb |= (mn>1.0f)?1u:0u;
            }
            bits |= pb<<oo;
        }
        out_bytes[(((size_t)(t*NB+b)*HP + hp)*WP + wp)*NG + og] = (uint8_t)bits;
    }
}

__global__ void __launch_bounds__(256) k_l2(const float* __restrict__ wg, const float* __restrict__ bg){
    __shared__ float wt[32*64];
    conv_lif_body<32,64,128,160>(g_spk1, (uint8_t*)g_spk2, wg, bg, wt);
}
__global__ void __launch_bounds__(256) k_l3(const float* __restrict__ wg, const float* __restrict__ bg){
    __shared__ float wt[64*64];
    conv_lif_body<64,64,64,80>(g_spk2, (uint8_t*)g_spk3, wg, bg, wt);
}
__global__ void __launch_bounds__(256) k_l4(const float* __restrict__ wg, const float* __restrict__ bg){
    __shared__ float wt[64*128];
    conv_lif_body<64,128,32,40>(g_spk3, (uint8_t*)g_spk4, wg, bg, wt);
}

// ------------- layer 5: conv 128->128 @16x20 + LIF + pool + time-sum of spikes -------------
// block handles one quarter q of output channels (32 ch) so weights fit in 16KB static smem.
__global__ void __launch_bounds__(256) k_l5(const float* __restrict__ wg, const float* __restrict__ bg){
    __shared__ float wt[128*32];                       // wt[c][ol], ol = o - q*32
    int q   = blockIdx.x / 40;                         // 4 quarters, 40 blocks each
    int rem = (blockIdx.x % 40)*256 + threadIdx.x;     // 0..10239
    for (int idx=threadIdx.x; idx<128*32; idx+=256) {
        int ol = idx & 31, c = idx >> 5;
        wt[c*32 + ol] = wg[(size_t)(q*32+ol)*128 + c];
    }
    __syncthreads();

    int ogl = rem & 15;                                // 2 out ch per thread
    int wp  = (rem >> 4) % 10;
    int hp  = (rem / 160) % 8;
    int b   = rem / 1280;
    int o0  = q*32 + ogl*2;

    float b0 = bg[o0], b1v = bg[o0+1];
    float m0[4]={0,0,0,0}, m1[4]={0,0,0,0};
    float c0cnt=0.0f, c1cnt=0.0f;

    #pragma unroll 1
    for (int t=0;t<T_STEPS;t++) {
        const uint4* ip = (const uint4*)g_spk4 + ((size_t)(t*NB+b)*16 + 2*hp)*20 + 2*wp;
        uint32_t mw[4][4];
        uint4 v;
        v = ip[0];  mw[0][0]=v.x; mw[0][1]=v.y; mw[0][2]=v.z; mw[0][3]=v.w;
        v = ip[1];  mw[1][0]=v.x; mw[1][1]=v.y; mw[1][2]=v.z; mw[1][3]=v.w;
        v = ip[20]; mw[2][0]=v.x; mw[2][1]=v.y; mw[2][2]=v.z; mw[2][3]=v.w;
        v = ip[21]; mw[3][0]=v.x; mw[3][1]=v.y; mw[3][2]=v.z; mw[3][3]=v.w;

        float cur0[4]={0,0,0,0}, cur1[4]={0,0,0,0};
        #pragma unroll
        for (int w=0;w<4;w++) {
            #pragma unroll
            for (int cb=0;cb<32;cb++) {
                float2 wv = *(const float2*)&wt[(w*32+cb)*32 + ogl*2];
                #pragma unroll
                for (int p=0;p<4;p++) {
                    float s = (float)((mw[p][w]>>cb)&1u);
                    cur0[p]=fmaf(wv.x,s,cur0[p]);
                    cur1[p]=fmaf(wv.y,s,cur1[p]);
                }
            }
        }
        uint32_t pb0=0, pb1=0;
        #pragma unroll
        for (int p=0;p<4;p++) {
            float mn0 = fmaf(0.95f,m0[p],cur0[p]+b0) - ((m0[p]>1.0f)?1.0f:0.0f);
            m0[p]=mn0; pb0 |= (mn0>1.0f)?1u:0u;
            float mn1 = fmaf(0.95f,m1[p],cur1[p]+b1v) - ((m1[p]>1.0f)?1.0f:0.0f);
            m1[p]=mn1; pb1 |= (mn1>1.0f)?1u:0u;
        }
        c0cnt += (float)pb0;
        c1cnt += (float)pb1;
    }
    g_S[((size_t)o0*80     + hp*10 + wp)*NB + b] = c0cnt;
    g_S[((size_t)(o0+1)*80 + hp*10 + wp)*NB + b] = c1cnt;
}

// ------------- fc1: [8,10240] @ [4096,10240]^T, spike -------------
__global__ void __launch_bounds__(256) k_fc1(const float* __restrict__ w,
                                             const float* __restrict__ bias){
    int tid = blockIdx.x*256 + threadIdx.x;   // 32768
    int b = tid & 7;
    int j = tid >> 3;
    const float* wr = w + (size_t)j*10240;
    float a0=0,a1=0,a2=0,a3=0;
    for (int k=0;k<10240;k+=4) {
        float4 wv = *(const float4*)(wr+k);
        a0 = fmaf(wv.x, g_S[(k+0)*NB+b], a0);
        a1 = fmaf(wv.y, g_S[(k+1)*NB+b], a1);
        a2 = fmaf(wv.z, g_S[(k+2)*NB+b], a2);
        a3 = fmaf(wv.w, g_S[(k+3)*NB+b], a3);
    }
    float mem = ((a0+a1)+(a2+a3)) + bias[j];
    g_spk1f[b*4096 + j] = (mem>1.0f)?1.0f:0.0f;
}

// ------------- fc2: [8,4096] @ [4,4096]^T -> out[8,4] -------------
__global__ void __launch_bounds__(1024) k_fc2(const float* __restrict__ w,
                                              const float* __restrict__ bias,
                                              float* __restrict__ out){
    int wid  = threadIdx.x >> 5;
    int lane = threadIdx.x & 31;
    int b = wid >> 2, i = wid & 3;
    float acc = 0.0f;
    for (int j = lane*4; j < 4096; j += 128) {
        float4 s  = *(const float4*)&g_spk1f[b*4096 + j];
        float4 wv = *(const float4*)&w[(size_t)i*4096 + j];
        acc = fmaf(wv.x, s.x, acc);
        acc = fmaf(wv.y, s.y, acc);
        acc = fmaf(wv.z, s.z, acc);
        acc = fmaf(wv.w, s.w, acc);
    }
    #pragma unroll
    for (int off=16; off; off>>=1) acc += __shfl_xor_sync(0xffffffffu, acc, off);
    if (lane == 0) out[b*4 + i] = acc + bias[i];
}

extern "C" void kernel_launch(void* const* d_in, const int* in_sizes, int n_in,
                              void* d_out, int out_size) {
    const float* x     = (const float*)d_in[0];
    const float* w1    = (const float*)d_in[1];
    const float* b1    = (const float*)d_in[2];
    const float* w2    = (const float*)d_in[3];
    const float* b2    = (const float*)d_in[4];
    const float* w3    = (const float*)d_in[5];
    const float* b3    = (const float*)d_in[6];
    const float* w4    = (const float*)d_in[7];
    const float* b4    = (const float*)d_in[8];
    const float* w5    = (const float*)d_in[9];
    const float* b5    = (const float*)d_in[10];
    const float* fc1_w = (const float*)d_in[11];
    const float* fc1_b = (const float*)d_in[12];
    const float* fc2_w = (const float*)d_in[13];
    const float* fc2_b = (const float*)d_in[14];

    k_l1<<<2560, 256>>>(x, w1, b1);        // 655360 threads
    k_l2<<<1280, 256>>>(w2, b2);           // 327680
    k_l3<<<320,  256>>>(w3, b3);           // 81920
    k_l4<<<160,  256>>>(w4, b4);           // 40960
    k_l5<<<160,  256>>>(w5, b5);           // 40960
    k_fc1<<<128, 256>>>(fc1_w, fc1_b);     // 32768
    k_fc2<<<1, 1024>>>(fc2_w, fc2_b, (float*)d_out);
}

// round 3
// speedup vs baseline: 2.6082x; 2.6082x over previous
#include <cuda_runtime.h>
#include <cstdint>
#include <cstddef>

#define T_STEPS 10
#define NB 8

// ---------------- scratch (device globals; no allocation) ----------------
__device__ uint32_t g_spk1[T_STEPS*NB*128*160];      // 32ch masks
__device__ uint32_t g_spk2[T_STEPS*NB*64*80*2];      // 64ch masks
__device__ uint32_t g_spk3[T_STEPS*NB*32*40*2];      // 64ch masks
__device__ uint32_t g_spk4[T_STEPS*NB*16*20*4];      // 128ch masks
__device__ float    g_S[10240*NB];                   // spike counts [k][b]
__device__ float    g_spk1f[NB*4096];                // fc1 spikes

__device__ __forceinline__ float lo32(unsigned long long v){ return __uint_as_float((uint32_t)v); }
__device__ __forceinline__ float hi32(unsigned long long v){ return __uint_as_float((uint32_t)(v>>32)); }

// ---------------- layer 1: conv 2->32 @256x320 + LIF + pool ----------------
// thread = (b, hp, wp, g in 0..3 [8ch], pos in 0..3). numerics identical to R1.
__global__ void __launch_bounds__(256) k_l1(const float* __restrict__ x,
                                            const float* __restrict__ w1,
                                            const float* __restrict__ b1) {
    int id  = blockIdx.x*256 + threadIdx.x;
    int pos = id & 3, dh = pos >> 1, dw = pos & 1;
    int g   = (id >> 2) & 3;
    int rid = id >> 4;
    int wp  = rid % 160; rid /= 160;
    int hp  = rid % 128;
    int b   = rid / 128;

    float w0[8], w1r[8], bb[8], m[8];
    #pragma unroll
    for (int oo=0; oo<8; oo++) {
        int o = g*8+oo;
        w0[oo] = w1[2*o]; w1r[oo] = w1[2*o+1]; bb[oo] = b1[o];
        m[oo]  = 0.0f;
    }

    const float* xb0 = x + ((size_t)b)*163840 + (2*hp+dh)*320 + (2*wp+dw);
    #pragma unroll 1
    for (int t=0; t<T_STEPS; t++) {
        const float* xb = xb0 + (size_t)t*NB*163840;
        float x0 = xb[0];
        float x1 = xb[81920];
        uint32_t sb = 0;
        #pragma unroll
        for (int oo=0; oo<8; oo++) {
            float cur = fmaf(w1r[oo], x1, w0[oo]*x0) + bb[oo];
            float mo  = m[oo];
            float mn  = fmaf(0.95f, mo, cur) - ((mo>1.0f)?1.0f:0.0f);
            m[oo] = mn;
            sb |= ((mn>1.0f)?1u:0u) << oo;
        }
        sb <<= (g*8);
        sb |= __shfl_xor_sync(0xffffffffu, sb, 1);
        sb |= __shfl_xor_sync(0xffffffffu, sb, 2);
        sb |= __shfl_xor_sync(0xffffffffu, sb, 4);
        sb |= __shfl_xor_sync(0xffffffffu, sb, 8);
        if ((id & 15) == 0)
            g_spk1[((size_t)(t*NB+b)*128 + hp)*160 + wp] = sb;
    }
}

// ------------- conv(1x1 over bitmask spikes)+LIF+pool, packed f32x2 predicated adds -------------
// Bit-exact vs R1's fmaf(w, s, cur) chain over ascending channels:
//   bit set   -> @p add.rn.f32x2 : rn(cur+w) == fmaf(w,1,cur)
//   bit clear -> accumulator untouched == fmaf(w,0,cur)
// blockIdx.y = out-channel group of OG channels. thread = (b,hp,wp,pos).
template<int CIN, int COUT, int OG, int HIN, int WIN, bool COUNT>
__device__ __forceinline__ void conv_body(const uint32_t* __restrict__ in,
                                          uint8_t* __restrict__ outb,
                                          const float* __restrict__ wg,
                                          const float* __restrict__ bg) {
    constexpr int WRD = CIN/32;
    constexpr int HP  = HIN/2, WP = WIN/2;
    constexpr int NBY = COUT/8;
    constexpr int NP  = OG/2;

    __shared__ __align__(16) float wt[CIN*OG];      // wt[c][o] (transposed)
    const int ob = blockIdx.y * OG;
    for (int idx = threadIdx.x; idx < CIN*OG; idx += 256) {
        int c = idx / OG, o = idx % OG;
        wt[c*OG + o] = wg[(size_t)(ob+o)*CIN + c];
    }
    __syncthreads();

    uint32_t sbase;
    asm("{ .reg .u64 t0; cvta.to.shared.u64 t0, %1; cvt.u32.u64 %0, t0; }"
        : "=r"(sbase) : "l"(wt));

    int id  = blockIdx.x*256 + threadIdx.x;
    int pos = id & 3, dh = pos >> 1, dw = pos & 1;
    int rid = id >> 2;
    int wp  = rid % WP; rid /= WP;
    int hp  = rid % HP;
    int b   = rid / HP;

    float bb[OG], m[OG], cnt[OG];
    #pragma unroll
    for (int c=0; c<OG; c++) { bb[c] = bg[ob+c]; m[c] = 0.0f; cnt[c] = 0.0f; }

    const uint32_t* ibase = in + (((size_t)b*HIN + 2*hp+dh)*WIN + (2*wp+dw))*WRD;
    const size_t tstride  = (size_t)NB*HIN*WIN*WRD;

    #pragma unroll 1
    for (int t=0; t<T_STEPS; t++) {
        const uint32_t* ip = ibase + (size_t)t*tstride;
        uint32_t mw[WRD];
        if constexpr (WRD == 1) {
            mw[0] = ip[0];
        } else if constexpr (WRD == 2) {
            uint2 v = *(const uint2*)ip; mw[0]=v.x; mw[1]=v.y;
        } else {
            uint4 v = *(const uint4*)ip; mw[0]=v.x; mw[1]=v.y; mw[2]=v.z; mw[3]=v.w;
        }

        unsigned long long acc[NP];
        #pragma unroll
        for (int p=0; p<NP; p++) acc[p] = 0ULL;

        #pragma unroll
        for (int c=0; c<CIN; c++) {
            uint32_t bit = (mw[c>>5] >> (c & 31)) & 1u;
            uint32_t addr = sbase + c*(OG*4);
            if constexpr (OG == 8) {
                asm volatile("{\n\t"
                    ".reg .pred p;\n\t"
                    ".reg .b64 wa,wb,wc,wd;\n\t"
                    "setp.ne.u32 p, %4, 0;\n\t"
                    "ld.shared.v2.u64 {wa,wb}, [%5];\n\t"
                    "ld.shared.v2.u64 {wc,wd}, [%5+16];\n\t"
                    "@p add.rn.f32x2 %0, %0, wa;\n\t"
                    "@p add.rn.f32x2 %1, %1, wb;\n\t"
                    "@p add.rn.f32x2 %2, %2, wc;\n\t"
                    "@p add.rn.f32x2 %3, %3, wd;\n\t"
                    "}"
                    : "+l"(acc[0]), "+l"(acc[1]), "+l"(acc[2]), "+l"(acc[3])
                    : "r"(bit), "r"(addr));
            } else {
                asm volatile("{\n\t"
                    ".reg .pred p;\n\t"
                    ".reg .b64 wa,wb;\n\t"
                    "setp.ne.u32 p, %2, 0;\n\t"
                    "ld.shared.v2.u64 {wa,wb}, [%3];\n\t"
                    "@p add.rn.f32x2 %0, %0, wa;\n\t"
                    "@p add.rn.f32x2 %1, %1, wb;\n\t"
                    "}"
                    : "+l"(acc[0]), "+l"(acc[1])
                    : "r"(bit), "r"(addr));
            }
        }

        uint32_t sb = 0;
        #pragma unroll
        for (int c=0; c<OG; c++) {
            float curc = (c & 1) ? hi32(acc[c>>1]) : lo32(acc[c>>1]);
            float cf = curc + bb[c];
            float mo = m[c];
            float mn = fmaf(0.95f, mo, cf) - ((mo>1.0f)?1.0f:0.0f);
            m[c] = mn;
            sb |= ((mn>1.0f)?1u:0u) << c;
        }
        sb |= __shfl_xor_sync(0xffffffffu, sb, 1);
        sb |= __shfl_xor_sync(0xffffffffu, sb, 2);

        if constexpr (COUNT) {
            #pragma unroll
            for (int c=0; c<OG; c++) cnt[c] += (float)((sb>>c)&1u);
        } else {
            if (pos == 0)
                outb[(((size_t)(t*NB+b)*HP + hp)*WP + wp)*NBY + blockIdx.y] = (uint8_t)sb;
        }
    }

    if constexpr (COUNT) {
        if (pos == 0) {
            #pragma unroll
            for (int c=0; c<OG; c++)
                g_S[((size_t)(ob+c)*(HP*WP) + hp*WP + wp)*NB + b] = cnt[c];
        }
    }
}

__global__ void __launch_bounds__(256) k_l2(const float* __restrict__ wg, const float* __restrict__ bg){
    conv_body<32,64,8,128,160,false>(g_spk1, (uint8_t*)g_spk2, wg, bg);
}
__global__ void __launch_bounds__(256) k_l3(const float* __restrict__ wg, const float* __restrict__ bg){
    conv_body<64,64,8,64,80,false>(g_spk2, (uint8_t*)g_spk3, wg, bg);
}
__global__ void __launch_bounds__(256) k_l4(const float* __restrict__ wg, const float* __restrict__ bg){
    conv_body<64,128,8,32,40,false>(g_spk3, (uint8_t*)g_spk4, wg, bg);
}
__global__ void __launch_bounds__(256) k_l5(const float* __restrict__ wg, const float* __restrict__ bg){
    conv_body<128,128,4,16,20,true>(g_spk4, nullptr, wg, bg);
}

// ------------- fc1: [8,10240] @ [4096,10240]^T, spike -------------
// Association EXACTLY as R1 (4 accumulators by k%4, ascending k), smem-staged tiles.
// 256 blocks x 128 threads; block = 16 j rows x 8 batches.
__global__ void __launch_bounds__(128) k_fc1(const float* __restrict__ w,
                                             const float* __restrict__ bias) {
    __shared__ __align__(16) float sw[16*260];   // 16 rows, padded stride 260
    __shared__ __align__(16) float ss[8*260];    // S transposed [b][k], padded
    int tid = threadIdx.x;
    int jl  = tid >> 3, b = tid & 7;
    int j   = blockIdx.x*16 + jl;

    float a0=0.f, a1=0.f, a2=0.f, a3=0.f;

    #pragma unroll 1
    for (int kt=0; kt<40; kt++) {
        __syncthreads();
        // stage W tile: rows blockIdx.x*16 .. +15, k = kt*256 .. +255 (coalesced)
        for (int i = tid; i < 1024; i += 128) {
            int r = i >> 6, c4 = i & 63;
            float4 v = *(const float4*)&w[(size_t)(blockIdx.x*16 + r)*10240 + kt*256 + c4*4];
            *(float4*)&sw[r*260 + c4*4] = v;
        }
        // stage S tile transposed
        for (int i = tid; i < 2048; i += 128) {
            int k = i >> 3, bi = i & 7;
            ss[bi*260 + k] = g_S[(size_t)(kt*256 + k)*8 + bi];
        }
        __syncthreads();

        #pragma unroll 4
        for (int kk=0; kk<256; kk+=4) {
            float4 wv = *(const float4*)&sw[jl*260 + kk];
            float4 sv = *(const float4*)&ss[b*260 + kk];
            a0 = fmaf(wv.x, sv.x, a0);
            a1 = fmaf(wv.y, sv.y, a1);
            a2 = fmaf(wv.z, sv.z, a2);
            a3 = fmaf(wv.w, sv.w, a3);
        }
    }
    float mem = ((a0+a1)+(a2+a3)) + bias[j];
    g_spk1f[b*4096 + j] = (mem>1.0f) ? 1.0f : 0.0f;
}

// ------------- fc2: [8,4096] @ [4,4096]^T -> out[8,4] (unchanged from R1) -------------
__global__ void __launch_bounds__(1024) k_fc2(const float* __restrict__ w,
                                              const float* __restrict__ bias,
                                              float* __restrict__ out) {
    int wid  = threadIdx.x >> 5;
    int lane = threadIdx.x & 31;
    int b = wid >> 2, i = wid & 3;
    float acc = 0.0f;
    for (int j = lane*4; j < 4096; j += 128) {
        float4 s  = *(const float4*)&g_spk1f[b*4096 + j];
        float4 wv = *(const float4*)&w[(size_t)i*4096 + j];
        acc = fmaf(wv.x, s.x, acc);
        acc = fmaf(wv.y, s.y, acc);
        acc = fmaf(wv.z, s.z, acc);
        acc = fmaf(wv.w, s.w, acc);
    }
    #pragma unroll
    for (int off=16; off; off>>=1) acc += __shfl_xor_sync(0xffffffffu, acc, off);
    if (lane == 0) out[b*4 + i] = acc + bias[i];
}

extern "C" void kernel_launch(void* const* d_in, const int* in_sizes, int n_in,
                              void* d_out, int out_size) {
    const float* x     = (const float*)d_in[0];
    const float* w1    = (const float*)d_in[1];
    const float* b1    = (const float*)d_in[2];
    const float* w2    = (const float*)d_in[3];
    const float* b2    = (const float*)d_in[4];
    const float* w3    = (const float*)d_in[5];
    const float* b3    = (const float*)d_in[6];
    const float* w4    = (const float*)d_in[7];
    const float* b4    = (const float*)d_in[8];
    const float* w5    = (const float*)d_in[9];
    const float* b5    = (const float*)d_in[10];
    const float* fc1_w = (const float*)d_in[11];
    const float* fc1_b = (const float*)d_in[12];
    const float* fc2_w = (const float*)d_in[13];
    const float* fc2_b = (const float*)d_in[14];

    k_l1<<<10240, 256>>>(x, w1, b1);
    { dim3 g(640, 8);  k_l2<<<g, 256>>>(w2, b2); }
    { dim3 g(160, 8);  k_l3<<<g, 256>>>(w3, b3); }
    { dim3 g(40, 16);  k_l4<<<g, 256>>>(w4, b4); }
    { dim3 g(10, 32);  k_l5<<<g, 256>>>(w5, b5); }
    k_fc1<<<256, 128>>>(fc1_w, fc1_b);
    k_fc2<<<1, 1024>>>(fc2_w, fc2_b, (float*)d_out);
}

// round 4
// speedup vs baseline: 3.0963x; 1.1872x over previous
#include <cuda_runtime.h>
#include <cstdint>
#include <cstddef>

#define T_STEPS 10
#define NB 8

// ---------------- scratch (device globals; no allocation) ----------------
__device__ uint32_t g_spk1[T_STEPS*NB*128*160];      // 32ch masks
__device__ uint32_t g_spk2[T_STEPS*NB*64*80*2];      // 64ch masks
__device__ uint32_t g_spk3[T_STEPS*NB*32*40*2];      // 64ch masks
__device__ uint32_t g_spk4[T_STEPS*NB*16*20*4];      // 128ch masks
__device__ float    g_S[10240*NB];                   // spike counts [k][b]
__device__ float    g_spk1f[NB*4096];                // fc1 spikes

__device__ __forceinline__ float lo32(unsigned long long v){ return __uint_as_float((uint32_t)v); }
__device__ __forceinline__ float hi32(unsigned long long v){ return __uint_as_float((uint32_t)(v>>32)); }

// ---------------- layer 1: conv 2->32 @256x320 + LIF + pool ----------------
__global__ void __launch_bounds__(256) k_l1(const float* __restrict__ x,
                                            const float* __restrict__ w1,
                                            const float* __restrict__ b1) {
    int id  = blockIdx.x*256 + threadIdx.x;
    int pos = id & 3, dh = pos >> 1, dw = pos & 1;
    int g   = (id >> 2) & 3;
    int rid = id >> 4;
    int wp  = rid % 160; rid /= 160;
    int hp  = rid % 128;
    int b   = rid / 128;

    float w0[8], w1r[8], bb[8], m[8];
    #pragma unroll
    for (int oo=0; oo<8; oo++) {
        int o = g*8+oo;
        w0[oo] = w1[2*o]; w1r[oo] = w1[2*o+1]; bb[oo] = b1[o];
        m[oo]  = 0.0f;
    }

    const float* xb0 = x + ((size_t)b)*163840 + (2*hp+dh)*320 + (2*wp+dw);
    #pragma unroll 1
    for (int t=0; t<T_STEPS; t++) {
        const float* xb = xb0 + (size_t)t*NB*163840;
        float x0 = xb[0];
        float x1 = xb[81920];
        uint32_t sb = 0;
        #pragma unroll
        for (int oo=0; oo<8; oo++) {
            float cur = fmaf(w1r[oo], x1, w0[oo]*x0) + bb[oo];
            float mo  = m[oo];
            float mn  = fmaf(0.95f, mo, cur) - ((mo>1.0f)?1.0f:0.0f);
            m[oo] = mn;
            sb |= ((mn>1.0f)?1u:0u) << oo;
        }
        sb <<= (g*8);
        sb |= __shfl_xor_sync(0xffffffffu, sb, 1);
        sb |= __shfl_xor_sync(0xffffffffu, sb, 2);
        sb |= __shfl_xor_sync(0xffffffffu, sb, 4);
        sb |= __shfl_xor_sync(0xffffffffu, sb, 8);
        if ((id & 15) == 0)
            g_spk1[((size_t)(t*NB+b)*128 + hp)*160 + wp] = sb;
    }
}

// ------------- conv(1x1 over bitmask spikes)+LIF+pool, packed f32x2 predicated adds -------------
// Bit-exact vs flat fmaf(w, s, cur) chain over ascending channels.
// Per channel: 1 LOP3(imm) for the bit test, LDS.128 at immediate offsets, 4(or 2) FADD2.
template<int CIN, int COUT, int OG, int HIN, int WIN, int BS, bool COUNT>
__device__ __forceinline__ void conv_body(const uint32_t* __restrict__ in,
                                          uint8_t* __restrict__ outb,
                                          const float* __restrict__ wg,
                                          const float* __restrict__ bg) {
    constexpr int WRD = CIN/32;
    constexpr int HP  = HIN/2, WP = WIN/2;
    constexpr int NBY = COUT/8;
    constexpr int NP  = OG/2;

    __shared__ __align__(16) float wt[CIN*OG];      // wt[c][o] (transposed)
    const int ob = blockIdx.y * OG;
    for (int idx = threadIdx.x; idx < CIN*OG; idx += BS) {
        int c = idx / OG, o = idx % OG;
        wt[c*OG + o] = wg[(size_t)(ob+o)*CIN + c];
    }
    __syncthreads();

    int id  = blockIdx.x*BS + threadIdx.x;
    int pos = id & 3, dh = pos >> 1, dw = pos & 1;
    int rid = id >> 2;
    int wp  = rid % WP; rid /= WP;
    int hp  = rid % HP;
    int b   = rid / HP;

    float bb[OG], m[OG], cnt[OG];
    #pragma unroll
    for (int c=0; c<OG; c++) { bb[c] = bg[ob+c]; m[c] = 0.0f; cnt[c] = 0.0f; }

    const uint32_t* ibase = in + (((size_t)b*HIN + 2*hp+dh)*WIN + (2*wp+dw))*WRD;
    const size_t tstride  = (size_t)NB*HIN*WIN*WRD;

    #pragma unroll 1
    for (int t=0; t<T_STEPS; t++) {
        const uint32_t* ip = ibase + (size_t)t*tstride;
        uint32_t mw[WRD];
        if constexpr (WRD == 1) {
            mw[0] = ip[0];
        } else if constexpr (WRD == 2) {
            uint2 v = *(const uint2*)ip; mw[0]=v.x; mw[1]=v.y;
        } else {
            uint4 v = *(const uint4*)ip; mw[0]=v.x; mw[1]=v.y; mw[2]=v.z; mw[3]=v.w;
        }

        unsigned long long acc[NP];
        #pragma unroll
        for (int p=0; p<NP; p++) acc[p] = 0ULL;

        #pragma unroll
        for (int c=0; c<CIN; c++) {
            // single LOP3 with immediate mask; setp fuses into predicate output
            uint32_t tb = mw[c>>5] & (1u << (c & 31));
            if constexpr (OG == 8) {
                ulonglong2 wv0 = *(const ulonglong2*)&wt[c*OG];     // LDS.128 [base+imm]
                ulonglong2 wv1 = *(const ulonglong2*)&wt[c*OG+4];
                asm volatile("{\n\t"
                    ".reg .pred p;\n\t"
                    "setp.ne.u32 p, %4, 0;\n\t"
                    "@p add.rn.f32x2 %0, %0, %5;\n\t"
                    "@p add.rn.f32x2 %1, %1, %6;\n\t"
                    "@p add.rn.f32x2 %2, %2, %7;\n\t"
                    "@p add.rn.f32x2 %3, %3, %8;\n\t"
                    "}"
                    : "+l"(acc[0]), "+l"(acc[1]), "+l"(acc[2]), "+l"(acc[3])
                    : "r"(tb), "l"(wv0.x), "l"(wv0.y), "l"(wv1.x), "l"(wv1.y));
            } else {
                ulonglong2 wv0 = *(const ulonglong2*)&wt[c*OG];
                asm volatile("{\n\t"
                    ".reg .pred p;\n\t"
                    "setp.ne.u32 p, %2, 0;\n\t"
                    "@p add.rn.f32x2 %0, %0, %3;\n\t"
                    "@p add.rn.f32x2 %1, %1, %4;\n\t"
                    "}"
                    : "+l"(acc[0]), "+l"(acc[1])
                    : "r"(tb), "l"(wv0.x), "l"(wv0.y));
            }
        }

        uint32_t sb = 0;
        #pragma unroll
        for (int c=0; c<OG; c++) {
            float curc = (c & 1) ? hi32(acc[c>>1]) : lo32(acc[c>>1]);
            float cf = curc + bb[c];
            float mo = m[c];
            float mn = fmaf(0.95f, mo, cf) - ((mo>1.0f)?1.0f:0.0f);
            m[c] = mn;
            sb |= ((mn>1.0f)?1u:0u) << c;
        }
        sb |= __shfl_xor_sync(0xffffffffu, sb, 1);
        sb |= __shfl_xor_sync(0xffffffffu, sb, 2);

        if constexpr (COUNT) {
            #pragma unroll
            for (int c=0; c<OG; c++) cnt[c] += (float)((sb>>c)&1u);
        } else {
            if (pos == 0)
                outb[(((size_t)(t*NB+b)*HP + hp)*WP + wp)*NBY + blockIdx.y] = (uint8_t)sb;
        }
    }

    if constexpr (COUNT) {
        if (pos == 0) {
            #pragma unroll
            for (int c=0; c<OG; c++)
                g_S[((size_t)(ob+c)*(HP*WP) + hp*WP + wp)*NB + b] = cnt[c];
        }
    }
}

__global__ void __launch_bounds__(256) k_l2(const float* __restrict__ wg, const float* __restrict__ bg){
    conv_body<32,64,8,128,160,256,false>(g_spk1, (uint8_t*)g_spk2, wg, bg);
}
__global__ void __launch_bounds__(256) k_l3(const float* __restrict__ wg, const float* __restrict__ bg){
    conv_body<64,64,8,64,80,256,false>(g_spk2, (uint8_t*)g_spk3, wg, bg);
}
__global__ void __launch_bounds__(128) k_l4(const float* __restrict__ wg, const float* __restrict__ bg){
    conv_body<64,128,8,32,40,128,false>(g_spk3, (uint8_t*)g_spk4, wg, bg);
}
__global__ void __launch_bounds__(128) k_l5(const float* __restrict__ wg, const float* __restrict__ bg){
    conv_body<128,128,4,16,20,128,true>(g_spk4, nullptr, wg, bg);
}

// ------------- fc1: [8,10240] @ [4096,10240]^T, spike -------------
__global__ void __launch_bounds__(128) k_fc1(const float* __restrict__ w,
                                             const float* __restrict__ bias) {
    __shared__ __align__(16) float sw[16*260];
    __shared__ __align__(16) float ss[8*260];
    int tid = threadIdx.x;
    int jl  = tid >> 3, b = tid & 7;
    int j   = blockIdx.x*16 + jl;

    float a0=0.f, a1=0.f, a2=0.f, a3=0.f;

    #pragma unroll 1
    for (int kt=0; kt<40; kt++) {
        __syncthreads();
        for (int i = tid; i < 1024; i += 128) {
            int r = i >> 6, c4 = i & 63;
            float4 v = *(const float4*)&w[(size_t)(blockIdx.x*16 + r)*10240 + kt*256 + c4*4];
            *(float4*)&sw[r*260 + c4*4] = v;
        }
        for (int i = tid; i < 2048; i += 128) {
            int k = i >> 3, bi = i & 7;
            ss[bi*260 + k] = g_S[(size_t)(kt*256 + k)*8 + bi];
        }
        __syncthreads();

        #pragma unroll 4
        for (int kk=0; kk<256; kk+=4) {
            float4 wv = *(const float4*)&sw[jl*260 + kk];
            float4 sv = *(const float4*)&ss[b*260 + kk];
            a0 = fmaf(wv.x, sv.x, a0);
            a1 = fmaf(wv.y, sv.y, a1);
            a2 = fmaf(wv.z, sv.z, a2);
            a3 = fmaf(wv.w, sv.w, a3);
        }
    }
    float mem = ((a0+a1)+(a2+a3)) + bias[j];
    g_spk1f[b*4096 + j] = (mem>1.0f) ? 1.0f : 0.0f;
}

// ------------- fc2: [8,4096] @ [4,4096]^T -> out[8,4] -------------
__global__ void __launch_bounds__(1024) k_fc2(const float* __restrict__ w,
                                              const float* __restrict__ bias,
                                              float* __restrict__ out) {
    int wid  = threadIdx.x >> 5;
    int lane = threadIdx.x & 31;
    int b = wid >> 2, i = wid & 3;
    float acc = 0.0f;
    for (int j = lane*4; j < 4096; j += 128) {
        float4 s  = *(const float4*)&g_spk1f[b*4096 + j];
        float4 wv = *(const float4*)&w[(size_t)i*4096 + j];
        acc = fmaf(wv.x, s.x, acc);
        acc = fmaf(wv.y, s.y, acc);
        acc = fmaf(wv.z, s.z, acc);
        acc = fmaf(wv.w, s.w, acc);
    }
    #pragma unroll
    for (int off=16; off; off>>=1) acc += __shfl_xor_sync(0xffffffffu, acc, off);
    if (lane == 0) out[b*4 + i] = acc + bias[i];
}

extern "C" void kernel_launch(void* const* d_in, const int* in_sizes, int n_in,
                              void* d_out, int out_size) {
    const float* x     = (const float*)d_in[0];
    const float* w1    = (const float*)d_in[1];
    const float* b1    = (const float*)d_in[2];
    const float* w2    = (const float*)d_in[3];
    const float* b2    = (const float*)d_in[4];
    const float* w3    = (const float*)d_in[5];
    const float* b3    = (const float*)d_in[6];
    const float* w4    = (const float*)d_in[7];
    const float* b4    = (const float*)d_in[8];
    const float* w5    = (const float*)d_in[9];
    const float* b5    = (const float*)d_in[10];
    const float* fc1_w = (const float*)d_in[11];
    const float* fc1_b = (const float*)d_in[12];
    const float* fc2_w = (const float*)d_in[13];
    const float* fc2_b = (const float*)d_in[14];

    k_l1<<<10240, 256>>>(x, w1, b1);
    { dim3 g(640, 8);  k_l2<<<g, 256>>>(w2, b2); }   // 256-thread blocks
    { dim3 g(160, 8);  k_l3<<<g, 256>>>(w3, b3); }
    { dim3 g(80, 16);  k_l4<<<g, 128>>>(w4, b4); }   // 128-thread blocks, 1280 CTAs
    { dim3 g(20, 32);  k_l5<<<g, 128>>>(w5, b5); }   // 640 CTAs
    k_fc1<<<256, 128>>>(fc1_w, fc1_b);
    k_fc2<<<1, 1024>>>(fc2_w, fc2_b, (float*)d_out);
}